// round 8
// baseline (speedup 1.0000x reference)
#include <cuda_runtime.h>
#include <math.h>

// Problem dims
#define Bc 64
#define Tc 512
#define Ic 512
#define Hc 1024
#define Oc 512
#define NCTA 128   // persistent grid (<=148 SMs -> all co-resident)

// Recurrence decomposition
#define NT 8       // column tiles of 128
#define KC 16      // K chunks of 64
#define KCH 64     // k per chunk
#define CT 128     // cols per tile
#define HSTRIDE 72 // padded row stride for transposed h in smem (16B aligned)

typedef unsigned long long ull;

// ---- packed f32x2 helpers (sm_100+; ptxas never auto-fuses these) ----
__device__ __forceinline__ ull pack2(float x, float y) {
    ull r; asm("mov.b64 %0, {%1,%2};" : "=l"(r) : "f"(x), "f"(y)); return r;
}
__device__ __forceinline__ float2 unpack2(ull v) {
    float2 f; asm("mov.b64 {%0,%1}, %2;" : "=f"(f.x), "=f"(f.y) : "l"(v)); return f;
}
__device__ __forceinline__ ull ffma2(ull a, ull b, ull c) {
    ull d; asm("fma.rn.f32x2 %0, %1, %2, %3;" : "=l"(d) : "l"(a), "l"(b), "l"(c));
    return d;
}

// Scratch (static __device__ allowed; cudaMalloc is not)
__device__ float g_xw[Tc * Bc * Hc];     // [t][b][h]  x@W_xh + b_h
__device__ float g_hall[Tc * Bc * Hc];   // [t][b][h]  hidden states
__device__ float g_part[KC * Bc * Hc];   // [kc][b][h] per-K-chunk partials (4MB)
__device__ unsigned g_bar;

// ---------------------------------------------------------------------------
__global__ void k_init() {
    if (threadIdx.x == 0) g_bar = 0u;
}

// ---------------------------------------------------------------------------
// GEMM 1: g_xw[t*B+b][h] = x[b*T+t][:] @ W_xh[:, h] + b_h[h]
// M=32768, N=1024, K=512. 128x128 tile, BK=8, 256 thr, 8x8 tile via FFMA2.
// ---------------------------------------------------------------------------
__global__ void __launch_bounds__(256) k_gemm_xw(const float* __restrict__ A,
                                                 const float* __restrict__ Bm,
                                                 const float* __restrict__ bias) {
    __shared__ float As[8][128];
    __shared__ float Bs[8][128];
    const int tid = threadIdx.x;
    const int tx = tid & 15;   // n
    const int ty = tid >> 4;   // m
    const int m0 = blockIdx.y * 128;
    const int n0 = blockIdx.x * 128;

    const int ar = tid >> 1, ac = (tid & 1) * 4;   // A: 128 rows x 8 k
    const int br = tid >> 5, bc = (tid & 31) * 4;  // B: 8 k x 128 n

    ull acc2[8][4];
#pragma unroll
    for (int i = 0; i < 8; ++i)
#pragma unroll
        for (int j = 0; j < 4; ++j) acc2[i][j] = 0ULL;

    for (int k0 = 0; k0 < Ic; k0 += 8) {
        float4 av = *(const float4*)&A[(size_t)(m0 + ar) * Ic + k0 + ac];
        float4 bv = *(const float4*)&Bm[(size_t)(k0 + br) * Hc + n0 + bc];
        __syncthreads();
        As[ac + 0][ar] = av.x; As[ac + 1][ar] = av.y;
        As[ac + 2][ar] = av.z; As[ac + 3][ar] = av.w;
        *(float4*)&Bs[br][bc] = bv;
        __syncthreads();
#pragma unroll
        for (int k = 0; k < 8; ++k) {
            float4 a0 = *(const float4*)&As[k][ty * 8];
            float4 a1 = *(const float4*)&As[k][ty * 8 + 4];
            float4 b0 = *(const float4*)&Bs[k][tx * 8];
            float4 b1 = *(const float4*)&Bs[k][tx * 8 + 4];
            ull bp[4] = {pack2(b0.x, b0.y), pack2(b0.z, b0.w),
                         pack2(b1.x, b1.y), pack2(b1.z, b1.w)};
            float ra[8] = {a0.x, a0.y, a0.z, a0.w, a1.x, a1.y, a1.z, a1.w};
#pragma unroll
            for (int i = 0; i < 8; ++i) {
                ull ad = pack2(ra[i], ra[i]);
#pragma unroll
                for (int j = 0; j < 4; ++j)
                    acc2[i][j] = ffma2(ad, bp[j], acc2[i][j]);
            }
        }
    }
#pragma unroll
    for (int i = 0; i < 8; ++i) {
        int r = m0 + ty * 8 + i;       // r = b*T + t
        int b = r >> 9;                // /512
        int t = r & 511;
        float* orow = g_xw + (size_t)(t * Bc + b) * Hc + n0 + tx * 8;
#pragma unroll
        for (int j = 0; j < 4; ++j) {
            float2 v = unpack2(acc2[i][j]);
            orow[2 * j + 0] = v.x + bias[n0 + tx * 8 + 2 * j + 0];
            orow[2 * j + 1] = v.y + bias[n0 + tx * 8 + 2 * j + 1];
        }
    }
}

// ---------------------------------------------------------------------------
// GEMM 2: out[b][t][o] = g_hall[t*B+b][:] @ W_hy[:, o] + b_y[o]
// M=32768, N=512, K=1024.
// ---------------------------------------------------------------------------
__global__ void __launch_bounds__(256) k_gemm_y(const float* __restrict__ Bm,
                                                const float* __restrict__ bias,
                                                float* __restrict__ out) {
    __shared__ float As[8][128];
    __shared__ float Bs[8][128];
    const int tid = threadIdx.x;
    const int tx = tid & 15;
    const int ty = tid >> 4;
    const int m0 = blockIdx.y * 128;
    const int n0 = blockIdx.x * 128;

    const int ar = tid >> 1, ac = (tid & 1) * 4;
    const int br = tid >> 5, bc = (tid & 31) * 4;

    ull acc2[8][4];
#pragma unroll
    for (int i = 0; i < 8; ++i)
#pragma unroll
        for (int j = 0; j < 4; ++j) acc2[i][j] = 0ULL;

    const float* A = g_hall;  // rows r = t*B + b, contiguous [32768,1024]
    for (int k0 = 0; k0 < Hc; k0 += 8) {
        float4 av = *(const float4*)&A[(size_t)(m0 + ar) * Hc + k0 + ac];
        float4 bv = *(const float4*)&Bm[(size_t)(k0 + br) * Oc + n0 + bc];
        __syncthreads();
        As[ac + 0][ar] = av.x; As[ac + 1][ar] = av.y;
        As[ac + 2][ar] = av.z; As[ac + 3][ar] = av.w;
        *(float4*)&Bs[br][bc] = bv;
        __syncthreads();
#pragma unroll
        for (int k = 0; k < 8; ++k) {
            float4 a0 = *(const float4*)&As[k][ty * 8];
            float4 a1 = *(const float4*)&As[k][ty * 8 + 4];
            float4 b0 = *(const float4*)&Bs[k][tx * 8];
            float4 b1 = *(const float4*)&Bs[k][tx * 8 + 4];
            ull bp[4] = {pack2(b0.x, b0.y), pack2(b0.z, b0.w),
                         pack2(b1.x, b1.y), pack2(b1.z, b1.w)};
            float ra[8] = {a0.x, a0.y, a0.z, a0.w, a1.x, a1.y, a1.z, a1.w};
#pragma unroll
            for (int i = 0; i < 8; ++i) {
                ull ad = pack2(ra[i], ra[i]);
#pragma unroll
                for (int j = 0; j < 4; ++j)
                    acc2[i][j] = ffma2(ad, bp[j], acc2[i][j]);
            }
        }
    }
#pragma unroll
    for (int i = 0; i < 8; ++i) {
        int r = m0 + ty * 8 + i;       // r = t*B + b
        int t = r >> 6;                // /64
        int b = r & 63;
        float* orow = out + ((size_t)b * Tc + t) * Oc + n0 + tx * 8;
#pragma unroll
        for (int j = 0; j < 4; ++j) {
            float2 v = unpack2(acc2[i][j]);
            orow[2 * j + 0] = v.x + bias[n0 + tx * 8 + 2 * j + 0];
            orow[2 * j + 1] = v.y + bias[n0 + tx * 8 + 2 * j + 1];
        }
    }
}

// ---------------------------------------------------------------------------
// Persistent recurrence kernel, K-split two-phase, FFMA2 inner loop.
// CTA (jt, kc): jt = col tile (128 cols), kc = K chunk (64 k).
// Phase A: partial[64][128] = h_{t-1}[:, kc*64:+64] @ Whh[kc*64:+64, jt*128:+128]
//          8x4 register tile packed as 8x2 f32x2 pairs.
// Phase B: 16384 threads sum 16 partials + xw, tanh, store h_t.
// ---------------------------------------------------------------------------
__global__ void __launch_bounds__(256, 1) k_rnn(const float* __restrict__ Whh) {
    extern __shared__ float sm[];
    float* w_sh = sm;                    // [64][128]  32KB
    float* h_sh = sm + KCH * CT;         // [64][HSTRIDE] transposed h: [k][r]

    const int tid = threadIdx.x;
    const int cta = blockIdx.x;
    const int jt = cta & (NT - 1);       // 0..7
    const int kc = cta >> 3;             // 0..15

    // Preload this CTA's W_hh slice: w_sh[k][j] = Whh[kc*64+k][jt*128+j]
    for (int e = tid; e < KCH * CT / 4; e += 256) {
        int k = e >> 5;                  // /32 float4 per row
        int j = (e & 31) * 4;
        *(float4*)&w_sh[k * CT + j] =
            *(const float4*)&Whh[(size_t)(kc * KCH + k) * Hc + jt * CT + j];
    }

    // Phase A thread tile: 8 rows x 4 cols
    const int r0 = (tid & 7) * 8;        // batch rows r0..r0+7
    const int j0 = (tid >> 3) * 4;       // cols j0..j0+3 (within tile)

    // Phase B mapping: 16384 active threads, each 1 row x 4 cols of h
    const int gid = cta * 256 + tid;
    const bool bact = gid < (Bc * Hc / 4);
    const int brow = gid >> 8;           // 0..63
    const int bcol = (gid & 255) * 4;    // 0..1020

    unsigned target = 0;

    for (int t = 0; t < Tc; ++t) {
        // ================= Phase A =================
        if (t > 0) {
            const float* hprev = g_hall + (size_t)(t - 1) * (Bc * Hc);
            // load h chunk transposed: h_sh[k][r]
#pragma unroll
            for (int i = 0; i < 4; ++i) {
                int g = tid + i * 256;          // 0..1023 float4 groups
                int r = g >> 4;                 // row
                int kq = (g & 15) * 4;          // k within chunk
                float4 v = *(const float4*)&hprev[(size_t)r * Hc + kc * KCH + kq];
                h_sh[(kq + 0) * HSTRIDE + r] = v.x;
                h_sh[(kq + 1) * HSTRIDE + r] = v.y;
                h_sh[(kq + 2) * HSTRIDE + r] = v.z;
                h_sh[(kq + 3) * HSTRIDE + r] = v.w;
            }
            __syncthreads();

            ull acc2[8][2];
#pragma unroll
            for (int i = 0; i < 8; ++i) { acc2[i][0] = 0ULL; acc2[i][1] = 0ULL; }

#pragma unroll 8
            for (int k = 0; k < KCH; ++k) {
                float4 w  = *(const float4*)&w_sh[k * CT + j0];
                ull wp0 = pack2(w.x, w.y);
                ull wp1 = pack2(w.z, w.w);
                float4 ha = *(const float4*)&h_sh[k * HSTRIDE + r0];
                float4 hb = *(const float4*)&h_sh[k * HSTRIDE + r0 + 4];
                float hv[8] = {ha.x, ha.y, ha.z, ha.w, hb.x, hb.y, hb.z, hb.w};
#pragma unroll
                for (int i = 0; i < 8; ++i) {
                    ull hd = pack2(hv[i], hv[i]);
                    acc2[i][0] = ffma2(hd, wp0, acc2[i][0]);
                    acc2[i][1] = ffma2(hd, wp1, acc2[i][1]);
                }
            }
            // write partials: g_part[kc][r][jt*128 + j]  (row stride Hc)
            float* pbase = g_part + (size_t)kc * (Bc * Hc) + jt * CT + j0;
#pragma unroll
            for (int i = 0; i < 8; ++i) {
                float2 p0 = unpack2(acc2[i][0]);
                float2 p1 = unpack2(acc2[i][1]);
                float4 v = make_float4(p0.x, p0.y, p1.x, p1.y);
                *(float4*)&pbase[(size_t)(r0 + i) * Hc] = v;
            }
        }

        // prefetch xw for phase B — independent of partials, hides under barrier
        float4 s = make_float4(0.f, 0.f, 0.f, 0.f);
        if (bact)
            s = *(const float4*)(g_xw + (size_t)t * (Bc * Hc) +
                                 (size_t)brow * Hc + bcol);

        // ---- grid barrier 1 ----
        target += NCTA;
        __syncthreads();
        if (tid == 0) {
            __threadfence();
            atomicAdd(&g_bar, 1u);
            while (*((volatile unsigned*)&g_bar) < target) { }
            __threadfence();
        }
        __syncthreads();

        // ================= Phase B =================
        if (bact) {
            if (t > 0) {
                const float* pb = g_part + (size_t)brow * Hc + bcol;
#pragma unroll
                for (int k2 = 0; k2 < KC; ++k2) {
                    // __ldcg: partial addresses repeat every step; bypass L1
                    float4 p = __ldcg((const float4*)(pb + (size_t)k2 * (Bc * Hc)));
                    s.x += p.x; s.y += p.y; s.z += p.z; s.w += p.w;
                }
            }
            float4 h;
            h.x = tanhf(s.x); h.y = tanhf(s.y);
            h.z = tanhf(s.z); h.w = tanhf(s.w);
            *(float4*)&g_hall[(size_t)t * (Bc * Hc) + (size_t)brow * Hc + bcol] = h;
        }

        // ---- grid barrier 2 ----
        target += NCTA;
        __syncthreads();
        if (tid == 0) {
            __threadfence();
            atomicAdd(&g_bar, 1u);
            while (*((volatile unsigned*)&g_bar) < target) { }
            __threadfence();
        }
        __syncthreads();
    }
}

// ---------------------------------------------------------------------------
extern "C" void kernel_launch(void* const* d_in, const int* in_sizes, int n_in,
                              void* d_out, int out_size) {
    const float* x    = (const float*)d_in[0];  // [64,512,512]
    const float* W_xh = (const float*)d_in[1];  // [512,1024]
    const float* W_hh = (const float*)d_in[2];  // [1024,1024]
    const float* b_h  = (const float*)d_in[3];  // [1024]
    const float* W_hy = (const float*)d_in[4];  // [1024,512]
    const float* b_y  = (const float*)d_in[5];  // [512]
    float* out = (float*)d_out;                 // [64,512,512]

    const int rnn_smem = (KCH * CT + KCH * HSTRIDE) * (int)sizeof(float); // ~50.4KB

    static bool attr_set = false;
    if (!attr_set) {
        cudaFuncSetAttribute(k_rnn, cudaFuncAttributeMaxDynamicSharedMemorySize,
                             rnn_smem);
        attr_set = true;
    }

    k_init<<<1, 32>>>();

    // xW projection: M=32768, N=1024
    dim3 gx(Hc / 128, (Bc * Tc) / 128);
    k_gemm_xw<<<gx, 256>>>(x, W_xh, b_h);

    // recurrence: persistent, 128 CTAs, two-phase K-split (FFMA2)
    k_rnn<<<NCTA, 256, rnn_smem>>>(W_hh);

    // output projection: M=32768, N=512
    dim3 gy(Oc / 128, (Bc * Tc) / 128);
    k_gemm_y<<<gy, 256>>>(W_hy, b_y, out);
}

// round 10
// speedup vs baseline: 2.5127x; 2.5127x over previous
#include <cuda_runtime.h>
#include <math.h>
#include <stdint.h>

// Problem dims
#define Bc 64
#define Tc 512
#define Ic 512
#define Hc 1024
#define Oc 512
#define NCTA 128   // persistent grid (<=148 SMs -> all co-resident)

// Recurrence decomposition
#define NT 8       // column tiles of 128
#define KC 16      // K chunks of 64
#define KCH 64     // k per chunk
#define CT 128     // cols per tile

// ---- tf32 helpers ----
__device__ __forceinline__ uint32_t f2tf32(float x) {
    uint32_t r; asm("cvt.rna.tf32.f32 %0, %1;" : "=r"(r) : "f"(x)); return r;
}
__device__ __forceinline__ void mma_tf32(float* c,
                                         const uint32_t* a, const uint32_t* b) {
    asm("mma.sync.aligned.m16n8k8.row.col.f32.tf32.tf32.f32 "
        "{%0,%1,%2,%3}, {%4,%5,%6,%7}, {%8,%9}, {%0,%1,%2,%3};"
        : "+f"(c[0]), "+f"(c[1]), "+f"(c[2]), "+f"(c[3])
        : "r"(a[0]), "r"(a[1]), "r"(a[2]), "r"(a[3]), "r"(b[0]), "r"(b[1]));
}

// Scratch (static __device__ allowed; cudaMalloc is not)
__device__ float g_xw[Tc * Bc * Hc];     // [t][b][h]  x@W_xh + b_h
__device__ float g_hall[Tc * Bc * Hc];   // [t][b][h]  hidden states (fp32)
__device__ float g_part[KC * Bc * Hc];   // [kc][b][h] per-K-chunk partials
__device__ float g_hhi[2 * Bc * Hc];     // ring: tf32 hi part of h
__device__ float g_hlo[2 * Bc * Hc];     // ring: tf32 lo part of h
__device__ unsigned g_bar;

// ---------------------------------------------------------------------------
__global__ void k_init() {
    if (threadIdx.x == 0) g_bar = 0u;
}

// ---------------------------------------------------------------------------
// Shared tf32 GEMM body: C[128x128 tile] = A[M,K] @ B[K,N], BK=16,
// 256 thr = 8 warps (wm 2 x wn 4), warp tile 64x32, m16n8k8 tf32 MMA.
// Epilogue is kernel-specific (index remap + bias).
// ---------------------------------------------------------------------------
#define GEMM_TF32_BODY(Aptr, Bptr, Kdim, Ndim)                                  \
    __shared__ uint32_t As[128][20];                                            \
    __shared__ uint32_t Bs[16][136];                                            \
    const int tid  = threadIdx.x;                                               \
    const int lane = tid & 31;                                                  \
    const int warp = tid >> 5;                                                  \
    const int wm = warp & 1, wn = warp >> 1;                                    \
    const int m0 = blockIdx.y * 128;                                            \
    const int n0 = blockIdx.x * 128;                                            \
    float acc[4][4][4];                                                         \
    _Pragma("unroll") for (int mi = 0; mi < 4; ++mi)                            \
    _Pragma("unroll") for (int ni = 0; ni < 4; ++ni)                            \
    _Pragma("unroll") for (int q = 0; q < 4; ++q) acc[mi][ni][q] = 0.f;         \
    for (int k0 = 0; k0 < (Kdim); k0 += 16) {                                   \
        float4 av[2], bv[2];                                                    \
        int arow[2], akq[2], brow[2], bnq[2];                                   \
        _Pragma("unroll") for (int i = 0; i < 2; ++i) {                         \
            int g = tid + i * 256;                                              \
            arow[i] = g >> 2; akq[i] = (g & 3) * 4;                             \
            av[i] = *(const float4*)&(Aptr)[(size_t)(m0 + arow[i]) * (Kdim)     \
                                            + k0 + akq[i]];                     \
            brow[i] = g >> 5; bnq[i] = (g & 31) * 4;                            \
            bv[i] = *(const float4*)&(Bptr)[(size_t)(k0 + brow[i]) * (Ndim)     \
                                            + n0 + bnq[i]];                     \
        }                                                                       \
        __syncthreads();                                                        \
        _Pragma("unroll") for (int i = 0; i < 2; ++i) {                         \
            uint4 ua = make_uint4(f2tf32(av[i].x), f2tf32(av[i].y),             \
                                  f2tf32(av[i].z), f2tf32(av[i].w));            \
            *(uint4*)&As[arow[i]][akq[i]] = ua;                                 \
            uint4 ub = make_uint4(f2tf32(bv[i].x), f2tf32(bv[i].y),             \
                                  f2tf32(bv[i].z), f2tf32(bv[i].w));            \
            *(uint4*)&Bs[brow[i]][bnq[i]] = ub;                                 \
        }                                                                       \
        __syncthreads();                                                        \
        _Pragma("unroll") for (int kb = 0; kb < 16; kb += 8) {                  \
            uint32_t afr[4][4];                                                 \
            _Pragma("unroll") for (int mi = 0; mi < 4; ++mi) {                  \
                int r = (lane >> 2) + mi * 16 + wm * 64;                        \
                int kk = kb + (lane & 3);                                       \
                afr[mi][0] = As[r][kk];                                         \
                afr[mi][1] = As[r + 8][kk];                                     \
                afr[mi][2] = As[r][kk + 4];                                     \
                afr[mi][3] = As[r + 8][kk + 4];                                 \
            }                                                                   \
            uint32_t bfr[4][2];                                                 \
            _Pragma("unroll") for (int ni = 0; ni < 4; ++ni) {                  \
                int c = (lane >> 2) + ni * 8 + wn * 32;                         \
                bfr[ni][0] = Bs[kb + (lane & 3)][c];                            \
                bfr[ni][1] = Bs[kb + (lane & 3) + 4][c];                        \
            }                                                                   \
            _Pragma("unroll") for (int mi = 0; mi < 4; ++mi)                    \
            _Pragma("unroll") for (int ni = 0; ni < 4; ++ni)                    \
                mma_tf32(acc[mi][ni], afr[mi], bfr[ni]);                        \
        }                                                                       \
    }

// GEMM 1: g_xw[t*B+b][h] = x[b*T+t][:] @ W_xh + b_h.  M=32768,N=1024,K=512
__global__ void __launch_bounds__(256) k_gemm_xw(const float* __restrict__ A,
                                                 const float* __restrict__ Bm,
                                                 const float* __restrict__ bias) {
    GEMM_TF32_BODY(A, Bm, Ic, Hc)
#pragma unroll
    for (int mi = 0; mi < 4; ++mi)
#pragma unroll
        for (int ni = 0; ni < 4; ++ni) {
            int r = m0 + wm * 64 + mi * 16 + (lane >> 2);
            int c = n0 + wn * 32 + ni * 8 + 2 * (lane & 3);
            float bx = bias[c], by = bias[c + 1];
            int b1i = r >> 9, t1i = r & 511;
            float* d0 = g_xw + (size_t)(t1i * Bc + b1i) * Hc + c;
            d0[0] = acc[mi][ni][0] + bx; d0[1] = acc[mi][ni][1] + by;
            int r2 = r + 8;
            int b2i = r2 >> 9, t2i = r2 & 511;
            float* d1 = g_xw + (size_t)(t2i * Bc + b2i) * Hc + c;
            d1[0] = acc[mi][ni][2] + bx; d1[1] = acc[mi][ni][3] + by;
        }
}

// GEMM 2: out[b][t][o] = g_hall[t*B+b][:] @ W_hy + b_y.  M=32768,N=512,K=1024
__global__ void __launch_bounds__(256) k_gemm_y(const float* __restrict__ Bm,
                                                const float* __restrict__ bias,
                                                float* __restrict__ out) {
    const float* A = g_hall;
    GEMM_TF32_BODY(A, Bm, Hc, Oc)
#pragma unroll
    for (int mi = 0; mi < 4; ++mi)
#pragma unroll
        for (int ni = 0; ni < 4; ++ni) {
            int r = m0 + wm * 64 + mi * 16 + (lane >> 2);
            int c = n0 + wn * 32 + ni * 8 + 2 * (lane & 3);
            float bx = bias[c], by = bias[c + 1];
            int t1i = r >> 6, b1i = r & 63;
            float* d0 = out + ((size_t)b1i * Tc + t1i) * Oc + c;
            d0[0] = acc[mi][ni][0] + bx; d0[1] = acc[mi][ni][1] + by;
            int r2 = r + 8;
            int t2i = r2 >> 6, b2i = r2 & 63;
            float* d1 = out + ((size_t)b2i * Tc + t2i) * Oc + c;
            d1[0] = acc[mi][ni][2] + bx; d1[1] = acc[mi][ni][3] + by;
        }
}

// ---------------------------------------------------------------------------
// Persistent recurrence, K-split two-phase, 3xTF32 MMA in phase A.
// CTA (jt, kc): partial[64][128] = h_prev[:, kc*64:+64] @ Whh[kc*64:+64, jt*128:+128]
// W hi/lo in SMEM (constant); h hi/lo from global ring (written in phase B).
// ---------------------------------------------------------------------------
__global__ void __launch_bounds__(256, 1) k_rnn(const float* __restrict__ Whh) {
    extern __shared__ uint32_t smu[];
    uint32_t* w_hi = smu;                       // [64][136]
    uint32_t* w_lo = smu + 64 * 136;            // [64][136]
    uint32_t* h_hi = smu + 2 * 64 * 136;        // [64][68]
    uint32_t* h_lo = smu + 2 * 64 * 136 + 64 * 68;

    const int tid  = threadIdx.x;
    const int lane = tid & 31;
    const int warp = tid >> 5;                  // 0..7 -> 16 cols each
    const int cta = blockIdx.x;
    const int jt = cta & (NT - 1);              // 0..7
    const int kc = cta >> 3;                    // 0..15

    // Preload W_hh slice, split hi/lo
    for (int e = tid; e < KCH * CT; e += 256) {
        int k = e >> 7, j = e & 127;
        float w = Whh[(size_t)(kc * KCH + k) * Hc + jt * CT + j];
        uint32_t hi = f2tf32(w);
        uint32_t lo = f2tf32(w - __uint_as_float(hi));
        w_hi[k * 136 + j] = hi;
        w_lo[k * 136 + j] = lo;
    }

    // Phase B mapping: 16384 active threads, each 1 row x 4 cols of h
    const int gid = cta * 256 + tid;
    const bool bact = gid < (Bc * Hc / 4);
    const int brow = gid >> 8;                  // 0..63
    const int bcol = (gid & 255) * 4;           // 0..1020

    unsigned target = 0;

    for (int t = 0; t < Tc; ++t) {
        // ================= Phase A =================
        if (t > 0) {
            const int ring = (t - 1) & 1;
            const float* phi = g_hhi + (size_t)ring * (Bc * Hc);
            const float* plo = g_hlo + (size_t)ring * (Bc * Hc);
            // load h chunk hi/lo: h_sh[r][k], row stride 68 (bank-clean)
#pragma unroll
            for (int i = 0; i < 4; ++i) {
                int g = tid + i * 256;          // 1024 uint4 groups
                int r = g >> 4, kq = (g & 15) * 4;
                size_t src = (size_t)r * Hc + kc * KCH + kq;
                // __ldcg: ring addresses repeat every 2 steps; bypass L1
                uint4 vh = __ldcg((const uint4*)(phi + src));
                uint4 vl = __ldcg((const uint4*)(plo + src));
                *(uint4*)&h_hi[r * 68 + kq] = vh;
                *(uint4*)&h_lo[r * 68 + kq] = vl;
            }
            __syncthreads();

            float acc[4][2][4];
#pragma unroll
            for (int mi = 0; mi < 4; ++mi)
#pragma unroll
                for (int ni = 0; ni < 2; ++ni)
#pragma unroll
                    for (int q = 0; q < 4; ++q) acc[mi][ni][q] = 0.f;

#pragma unroll
            for (int kb8 = 0; kb8 < 8; ++kb8) {
                const int kb = kb8 * 8;
                uint32_t ahi[4][4], alo[4][4];
#pragma unroll
                for (int mi = 0; mi < 4; ++mi) {
                    int r = (lane >> 2) + mi * 16;
                    int kk = kb + (lane & 3);
                    ahi[mi][0] = h_hi[r * 68 + kk];
                    ahi[mi][1] = h_hi[(r + 8) * 68 + kk];
                    ahi[mi][2] = h_hi[r * 68 + kk + 4];
                    ahi[mi][3] = h_hi[(r + 8) * 68 + kk + 4];
                    alo[mi][0] = h_lo[r * 68 + kk];
                    alo[mi][1] = h_lo[(r + 8) * 68 + kk];
                    alo[mi][2] = h_lo[r * 68 + kk + 4];
                    alo[mi][3] = h_lo[(r + 8) * 68 + kk + 4];
                }
                uint32_t bhi[2][2], blo[2][2];
#pragma unroll
                for (int ni = 0; ni < 2; ++ni) {
                    int c = (lane >> 2) + ni * 8 + warp * 16;
                    int kk = kb + (lane & 3);
                    bhi[ni][0] = w_hi[kk * 136 + c];
                    bhi[ni][1] = w_hi[(kk + 4) * 136 + c];
                    blo[ni][0] = w_lo[kk * 136 + c];
                    blo[ni][1] = w_lo[(kk + 4) * 136 + c];
                }
#pragma unroll
                for (int mi = 0; mi < 4; ++mi)
#pragma unroll
                    for (int ni = 0; ni < 2; ++ni) {
                        mma_tf32(acc[mi][ni], ahi[mi], bhi[ni]);  // hi*hi
                        mma_tf32(acc[mi][ni], ahi[mi], blo[ni]);  // hi*lo
                        mma_tf32(acc[mi][ni], alo[mi], bhi[ni]);  // lo*hi
                    }
            }
            // write partials: g_part[kc][row][jt*128 + col]
#pragma unroll
            for (int mi = 0; mi < 4; ++mi)
#pragma unroll
                for (int ni = 0; ni < 2; ++ni) {
                    int row = (lane >> 2) + mi * 16;
                    int col = warp * 16 + ni * 8 + 2 * (lane & 3);
                    float* p = g_part + (size_t)kc * (Bc * Hc)
                             + (size_t)row * Hc + jt * CT + col;
                    *(float2*)p = make_float2(acc[mi][ni][0], acc[mi][ni][1]);
                    *(float2*)(p + 8 * Hc) =
                        make_float2(acc[mi][ni][2], acc[mi][ni][3]);
                }
        }

        // prefetch xw for phase B (independent; hides under barrier)
        float4 s = make_float4(0.f, 0.f, 0.f, 0.f);
        if (bact)
            s = *(const float4*)(g_xw + (size_t)t * (Bc * Hc) +
                                 (size_t)brow * Hc + bcol);

        // ---- grid barrier 1 ----
        target += NCTA;
        __syncthreads();
        if (tid == 0) {
            __threadfence();
            atomicAdd(&g_bar, 1u);
            while (*((volatile unsigned*)&g_bar) < target) { }
            __threadfence();
        }
        __syncthreads();

        // ================= Phase B =================
        if (bact) {
            if (t > 0) {
                const float* pb = g_part + (size_t)brow * Hc + bcol;
#pragma unroll
                for (int k2 = 0; k2 < KC; ++k2) {
                    float4 p = __ldcg((const float4*)(pb + (size_t)k2 * (Bc * Hc)));
                    s.x += p.x; s.y += p.y; s.z += p.z; s.w += p.w;
                }
            }
            float4 h;
            h.x = tanhf(s.x); h.y = tanhf(s.y);
            h.z = tanhf(s.z); h.w = tanhf(s.w);
            size_t dst = (size_t)brow * Hc + bcol;
            *(float4*)&g_hall[(size_t)t * (Bc * Hc) + dst] = h;
            // split hi/lo for next step's 3xTF32 phase A (ring slot t&1)
            uint4 hi = make_uint4(f2tf32(h.x), f2tf32(h.y),
                                  f2tf32(h.z), f2tf32(h.w));
            uint4 lo = make_uint4(
                f2tf32(h.x - __uint_as_float(hi.x)),
                f2tf32(h.y - __uint_as_float(hi.y)),
                f2tf32(h.z - __uint_as_float(hi.z)),
                f2tf32(h.w - __uint_as_float(hi.w)));
            size_t rb = (size_t)(t & 1) * (Bc * Hc) + dst;
            *(uint4*)&g_hhi[rb] = hi;
            *(uint4*)&g_hlo[rb] = lo;
        }

        // ---- grid barrier 2 ----
        target += NCTA;
        __syncthreads();
        if (tid == 0) {
            __threadfence();
            atomicAdd(&g_bar, 1u);
            while (*((volatile unsigned*)&g_bar) < target) { }
            __threadfence();
        }
        __syncthreads();
    }
}

// ---------------------------------------------------------------------------
extern "C" void kernel_launch(void* const* d_in, const int* in_sizes, int n_in,
                              void* d_out, int out_size) {
    const float* x    = (const float*)d_in[0];  // [64,512,512]
    const float* W_xh = (const float*)d_in[1];  // [512,1024]
    const float* W_hh = (const float*)d_in[2];  // [1024,1024]
    const float* b_h  = (const float*)d_in[3];  // [1024]
    const float* W_hy = (const float*)d_in[4];  // [1024,512]
    const float* b_y  = (const float*)d_in[5];  // [512]
    float* out = (float*)d_out;                 // [64,512,512]

    const int rnn_smem = (2 * 64 * 136 + 2 * 64 * 68) * (int)sizeof(uint32_t);

    static bool attr_set = false;
    if (!attr_set) {
        cudaFuncSetAttribute(k_rnn, cudaFuncAttributeMaxDynamicSharedMemorySize,
                             rnn_smem);
        attr_set = true;
    }

    k_init<<<1, 32>>>();

    // xW projection: M=32768, N=1024 (tf32 MMA)
    dim3 gx(Hc / 128, (Bc * Tc) / 128);
    k_gemm_xw<<<gx, 256>>>(x, W_xh, b_h);

    // recurrence: persistent, 128 CTAs, two-phase K-split (3xTF32 MMA)
    k_rnn<<<NCTA, 256, rnn_smem>>>(W_hh);

    // output projection: M=32768, N=512 (tf32 MMA)
    dim3 gy(Oc / 128, (Bc * Tc) / 128);
    k_gemm_y<<<gy, 256>>>(W_hy, b_y, out);
}

// round 11
// speedup vs baseline: 2.9978x; 1.1931x over previous
#include <cuda_runtime.h>
#include <math.h>
#include <stdint.h>

// Problem dims
#define Bc 64
#define Tc 512
#define Ic 512
#define Hc 1024
#define Oc 512
#define NCTA 128   // persistent grid (<=148 SMs -> all co-resident)

// Recurrence decomposition
#define NT 8       // column tiles of 128
#define KC 16      // K chunks of 64
#define KCH 64     // k per chunk
#define CT 128     // cols per tile
#define H2 (Hc/2)  // packed bf16x2 pairs per row

// ---- tf32 helpers (big GEMMs) ----
__device__ __forceinline__ uint32_t f2tf32(float x) {
    uint32_t r; asm("cvt.rna.tf32.f32 %0, %1;" : "=r"(r) : "f"(x)); return r;
}
__device__ __forceinline__ void mma_tf32(float* c,
                                         const uint32_t* a, const uint32_t* b) {
    asm("mma.sync.aligned.m16n8k8.row.col.f32.tf32.tf32.f32 "
        "{%0,%1,%2,%3}, {%4,%5,%6,%7}, {%8,%9}, {%0,%1,%2,%3};"
        : "+f"(c[0]), "+f"(c[1]), "+f"(c[2]), "+f"(c[3])
        : "r"(a[0]), "r"(a[1]), "r"(a[2]), "r"(a[3]), "r"(b[0]), "r"(b[1]));
}

// ---- bf16 helpers (recurrence) ----
// pack (x->lower, y->upper); exact split: hi = bf16x2(x,y), lo = bf16x2(resid)
__device__ __forceinline__ void split_bf16x2(float x, float y,
                                             uint32_t& hi, uint32_t& lo) {
    uint32_t h;
    asm("cvt.rn.bf16x2.f32 %0, %1, %2;" : "=r"(h) : "f"(y), "f"(x));
    float xh = __uint_as_float(h << 16);
    float yh = __uint_as_float(h & 0xFFFF0000u);
    asm("cvt.rn.bf16x2.f32 %0, %1, %2;" : "=r"(lo) : "f"(y - yh), "f"(x - xh));
    hi = h;
}
__device__ __forceinline__ void mma_bf16(float* c,
                                         const uint32_t* a, const uint32_t* b) {
    asm("mma.sync.aligned.m16n8k16.row.col.f32.bf16.bf16.f32 "
        "{%0,%1,%2,%3}, {%4,%5,%6,%7}, {%8,%9}, {%0,%1,%2,%3};"
        : "+f"(c[0]), "+f"(c[1]), "+f"(c[2]), "+f"(c[3])
        : "r"(a[0]), "r"(a[1]), "r"(a[2]), "r"(a[3]), "r"(b[0]), "r"(b[1]));
}

// Scratch (static __device__ allowed; cudaMalloc is not)
__device__ float g_xw[Tc * Bc * Hc];        // [t][b][h]  x@W_xh + b_h
__device__ float g_hall[Tc * Bc * Hc];      // [t][b][h]  hidden states (fp32)
__device__ float g_part[KC * Bc * Hc];      // [kc][b][h] per-K-chunk partials
__device__ uint32_t g_hpk_hi[2 * Bc * H2];  // ring: packed bf16x2 hi of h
__device__ uint32_t g_hpk_lo[2 * Bc * H2];  // ring: packed bf16x2 lo of h
__device__ unsigned g_bar;

// ---------------------------------------------------------------------------
__global__ void k_init() {
    if (threadIdx.x == 0) g_bar = 0u;
}

// ---------------------------------------------------------------------------
// Shared tf32 GEMM body: C[128x128 tile] = A[M,K] @ B[K,N], BK=16,
// 256 thr = 8 warps (wm 2 x wn 4), warp tile 64x32, m16n8k8 tf32 MMA.
// ---------------------------------------------------------------------------
#define GEMM_TF32_BODY(Aptr, Bptr, Kdim, Ndim)                                  \
    __shared__ uint32_t As[128][20];                                            \
    __shared__ uint32_t Bs[16][136];                                            \
    const int tid  = threadIdx.x;                                               \
    const int lane = tid & 31;                                                  \
    const int warp = tid >> 5;                                                  \
    const int wm = warp & 1, wn = warp >> 1;                                    \
    const int m0 = blockIdx.y * 128;                                            \
    const int n0 = blockIdx.x * 128;                                            \
    float acc[4][4][4];                                                         \
    _Pragma("unroll") for (int mi = 0; mi < 4; ++mi)                            \
    _Pragma("unroll") for (int ni = 0; ni < 4; ++ni)                            \
    _Pragma("unroll") for (int q = 0; q < 4; ++q) acc[mi][ni][q] = 0.f;         \
    for (int k0 = 0; k0 < (Kdim); k0 += 16) {                                   \
        float4 av[2], bv[2];                                                    \
        int arow[2], akq[2], brow[2], bnq[2];                                   \
        _Pragma("unroll") for (int i = 0; i < 2; ++i) {                         \
            int g = tid + i * 256;                                              \
            arow[i] = g >> 2; akq[i] = (g & 3) * 4;                             \
            av[i] = *(const float4*)&(Aptr)[(size_t)(m0 + arow[i]) * (Kdim)     \
                                            + k0 + akq[i]];                     \
            brow[i] = g >> 5; bnq[i] = (g & 31) * 4;                            \
            bv[i] = *(const float4*)&(Bptr)[(size_t)(k0 + brow[i]) * (Ndim)     \
                                            + n0 + bnq[i]];                     \
        }                                                                       \
        __syncthreads();                                                        \
        _Pragma("unroll") for (int i = 0; i < 2; ++i) {                         \
            uint4 ua = make_uint4(f2tf32(av[i].x), f2tf32(av[i].y),             \
                                  f2tf32(av[i].z), f2tf32(av[i].w));            \
            *(uint4*)&As[arow[i]][akq[i]] = ua;                                 \
            uint4 ub = make_uint4(f2tf32(bv[i].x), f2tf32(bv[i].y),             \
                                  f2tf32(bv[i].z), f2tf32(bv[i].w));            \
            *(uint4*)&Bs[brow[i]][bnq[i]] = ub;                                 \
        }                                                                       \
        __syncthreads();                                                        \
        _Pragma("unroll") for (int kb = 0; kb < 16; kb += 8) {                  \
            uint32_t afr[4][4];                                                 \
            _Pragma("unroll") for (int mi = 0; mi < 4; ++mi) {                  \
                int r = (lane >> 2) + mi * 16 + wm * 64;                        \
                int kk = kb + (lane & 3);                                       \
                afr[mi][0] = As[r][kk];                                         \
                afr[mi][1] = As[r + 8][kk];                                     \
                afr[mi][2] = As[r][kk + 4];                                     \
                afr[mi][3] = As[r + 8][kk + 4];                                 \
            }                                                                   \
            uint32_t bfr[4][2];                                                 \
            _Pragma("unroll") for (int ni = 0; ni < 4; ++ni) {                  \
                int c = (lane >> 2) + ni * 8 + wn * 32;                         \
                bfr[ni][0] = Bs[kb + (lane & 3)][c];                            \
                bfr[ni][1] = Bs[kb + (lane & 3) + 4][c];                        \
            }                                                                   \
            _Pragma("unroll") for (int mi = 0; mi < 4; ++mi)                    \
            _Pragma("unroll") for (int ni = 0; ni < 4; ++ni)                    \
                mma_tf32(acc[mi][ni], afr[mi], bfr[ni]);                        \
        }                                                                       \
    }

// GEMM 1: g_xw[t*B+b][h] = x[b*T+t][:] @ W_xh + b_h.  M=32768,N=1024,K=512
__global__ void __launch_bounds__(256) k_gemm_xw(const float* __restrict__ A,
                                                 const float* __restrict__ Bm,
                                                 const float* __restrict__ bias) {
    GEMM_TF32_BODY(A, Bm, Ic, Hc)
#pragma unroll
    for (int mi = 0; mi < 4; ++mi)
#pragma unroll
        for (int ni = 0; ni < 4; ++ni) {
            int r = m0 + wm * 64 + mi * 16 + (lane >> 2);
            int c = n0 + wn * 32 + ni * 8 + 2 * (lane & 3);
            float bx = bias[c], by = bias[c + 1];
            int b1i = r >> 9, t1i = r & 511;
            float* d0 = g_xw + (size_t)(t1i * Bc + b1i) * Hc + c;
            d0[0] = acc[mi][ni][0] + bx; d0[1] = acc[mi][ni][1] + by;
            int r2 = r + 8;
            int b2i = r2 >> 9, t2i = r2 & 511;
            float* d1 = g_xw + (size_t)(t2i * Bc + b2i) * Hc + c;
            d1[0] = acc[mi][ni][2] + bx; d1[1] = acc[mi][ni][3] + by;
        }
}

// GEMM 2: out[b][t][o] = g_hall[t*B+b][:] @ W_hy + b_y.  M=32768,N=512,K=1024
__global__ void __launch_bounds__(256) k_gemm_y(const float* __restrict__ Bm,
                                                const float* __restrict__ bias,
                                                float* __restrict__ out) {
    const float* A = g_hall;
    GEMM_TF32_BODY(A, Bm, Hc, Oc)
#pragma unroll
    for (int mi = 0; mi < 4; ++mi)
#pragma unroll
        for (int ni = 0; ni < 4; ++ni) {
            int r = m0 + wm * 64 + mi * 16 + (lane >> 2);
            int c = n0 + wn * 32 + ni * 8 + 2 * (lane & 3);
            float bx = bias[c], by = bias[c + 1];
            int t1i = r >> 6, b1i = r & 63;
            float* d0 = out + ((size_t)b1i * Tc + t1i) * Oc + c;
            d0[0] = acc[mi][ni][0] + bx; d0[1] = acc[mi][ni][1] + by;
            int r2 = r + 8;
            int t2i = r2 >> 6, b2i = r2 & 63;
            float* d1 = out + ((size_t)b2i * Tc + t2i) * Oc + c;
            d1[0] = acc[mi][ni][2] + bx; d1[1] = acc[mi][ni][3] + by;
        }
}

// ---------------------------------------------------------------------------
// Persistent recurrence, K-split two-phase, bf16x3 m16n8k16 MMA in phase A.
// CTA (jt, kc): partial[64][128] = h_prev[:, kc*64:+64] @ Whh[kc*64:+64, jt*128:+128]
// h@W ~= hi@Wh + hi@Wl + lo@Wh (exact splits; missing lo@Wl ~ 2^-18 rel).
// W hi/lo packed bf16x2 in SMEM [n][k2] (constant); h hi/lo from packed ring.
// ---------------------------------------------------------------------------
__global__ void __launch_bounds__(256, 1) k_rnn(const float* __restrict__ Whh) {
    extern __shared__ uint32_t smu[];
    uint32_t* w_hi = smu;                       // [128 n][36]  (32 k2 used)
    uint32_t* w_lo = smu + 128 * 36;            // [128 n][36]
    uint32_t* h_hi = smu + 2 * 128 * 36;        // [64 r][36]
    uint32_t* h_lo = smu + 2 * 128 * 36 + 64 * 36;

    const int tid  = threadIdx.x;
    const int lane = tid & 31;
    const int warp = tid >> 5;                  // 0..7 -> 16 cols each
    const int cta = blockIdx.x;
    const int jt = cta & (NT - 1);              // 0..7
    const int kc = cta >> 3;                    // 0..15

    // Preload W_hh slice, split + pack (k even -> lower, k+1 -> upper)
    for (int e = tid; e < CT * (KCH / 2); e += 256) {
        int n = e & 127, k2 = e >> 7;           // k2 0..31
        const float* wp = Whh + (size_t)(kc * KCH + 2 * k2) * Hc + jt * CT + n;
        float w0 = wp[0], w1 = wp[Hc];
        uint32_t hi, lo;
        split_bf16x2(w0, w1, hi, lo);
        w_hi[n * 36 + k2] = hi;
        w_lo[n * 36 + k2] = lo;
    }

    // Phase B mapping: 16384 active threads, each 1 row x 4 cols of h
    const int gid = cta * 256 + tid;
    const bool bact = gid < (Bc * Hc / 4);
    const int brow = gid >> 8;                  // 0..63
    const int bcol = (gid & 255) * 4;           // 0..1020

    unsigned target = 0;

    for (int t = 0; t < Tc; ++t) {
        // ================= Phase A =================
        if (t > 0) {
            const int ring = (t - 1) & 1;
            const uint32_t* phi = g_hpk_hi + (size_t)ring * (Bc * H2);
            const uint32_t* plo = g_hpk_lo + (size_t)ring * (Bc * H2);
            // load h chunk (packed pairs): h_sh[r][k2], 32 k2 per row
#pragma unroll
            for (int i = 0; i < 2; ++i) {
                int g = tid + i * 256;          // 512 uint4 groups
                int r = g >> 3, kq = (g & 7) * 4;
                size_t src = (size_t)r * H2 + kc * (KCH / 2) + kq;
                // __ldcg: ring addresses repeat every 2 steps; bypass L1
                uint4 vh = __ldcg((const uint4*)(phi + src));
                uint4 vl = __ldcg((const uint4*)(plo + src));
                *(uint4*)&h_hi[r * 36 + kq] = vh;
                *(uint4*)&h_lo[r * 36 + kq] = vl;
            }
            __syncthreads();

            float acc[4][2][4];
#pragma unroll
            for (int mi = 0; mi < 4; ++mi)
#pragma unroll
                for (int ni = 0; ni < 2; ++ni)
#pragma unroll
                    for (int q = 0; q < 4; ++q) acc[mi][ni][q] = 0.f;

#pragma unroll
            for (int s = 0; s < 4; ++s) {       // four k16 slabs
                const int ks = s * 8;
                uint32_t ahi[4][4], alo[4][4];
#pragma unroll
                for (int mi = 0; mi < 4; ++mi) {
                    int r = (lane >> 2) + mi * 16;
                    int kk = ks + (lane & 3);
                    ahi[mi][0] = h_hi[r * 36 + kk];
                    ahi[mi][1] = h_hi[(r + 8) * 36 + kk];
                    ahi[mi][2] = h_hi[r * 36 + kk + 4];
                    ahi[mi][3] = h_hi[(r + 8) * 36 + kk + 4];
                    alo[mi][0] = h_lo[r * 36 + kk];
                    alo[mi][1] = h_lo[(r + 8) * 36 + kk];
                    alo[mi][2] = h_lo[r * 36 + kk + 4];
                    alo[mi][3] = h_lo[(r + 8) * 36 + kk + 4];
                }
                uint32_t bhi[2][2], blo[2][2];
#pragma unroll
                for (int ni = 0; ni < 2; ++ni) {
                    int n = (lane >> 2) + ni * 8 + warp * 16;
                    int kk = ks + (lane & 3);
                    bhi[ni][0] = w_hi[n * 36 + kk];
                    bhi[ni][1] = w_hi[n * 36 + kk + 4];
                    blo[ni][0] = w_lo[n * 36 + kk];
                    blo[ni][1] = w_lo[n * 36 + kk + 4];
                }
#pragma unroll
                for (int mi = 0; mi < 4; ++mi)
#pragma unroll
                    for (int ni = 0; ni < 2; ++ni) {
                        mma_bf16(acc[mi][ni], ahi[mi], bhi[ni]);  // hi*Whi
                        mma_bf16(acc[mi][ni], ahi[mi], blo[ni]);  // hi*Wlo
                        mma_bf16(acc[mi][ni], alo[mi], bhi[ni]);  // lo*Whi
                    }
            }
            // write partials: g_part[kc][row][jt*128 + col]
#pragma unroll
            for (int mi = 0; mi < 4; ++mi)
#pragma unroll
                for (int ni = 0; ni < 2; ++ni) {
                    int row = (lane >> 2) + mi * 16;
                    int col = warp * 16 + ni * 8 + 2 * (lane & 3);
                    float* p = g_part + (size_t)kc * (Bc * Hc)
                             + (size_t)row * Hc + jt * CT + col;
                    *(float2*)p = make_float2(acc[mi][ni][0], acc[mi][ni][1]);
                    *(float2*)(p + 8 * Hc) =
                        make_float2(acc[mi][ni][2], acc[mi][ni][3]);
                }
        }

        // prefetch xw for phase B (independent; hides under barrier)
        float4 sx = make_float4(0.f, 0.f, 0.f, 0.f);
        if (bact)
            sx = *(const float4*)(g_xw + (size_t)t * (Bc * Hc) +
                                  (size_t)brow * Hc + bcol);

        // ---- grid barrier 1 ----
        target += NCTA;
        __syncthreads();
        if (tid == 0) {
            __threadfence();
            atomicAdd(&g_bar, 1u);
            while (*((volatile unsigned*)&g_bar) < target) { }
            __threadfence();
        }
        __syncthreads();

        // ================= Phase B =================
        if (bact) {
            if (t > 0) {
                const float* pb = g_part + (size_t)brow * Hc + bcol;
#pragma unroll
                for (int k2 = 0; k2 < KC; ++k2) {
                    float4 p = __ldcg((const float4*)(pb + (size_t)k2 * (Bc * Hc)));
                    sx.x += p.x; sx.y += p.y; sx.z += p.z; sx.w += p.w;
                }
            }
            float4 h;
            h.x = tanhf(sx.x); h.y = tanhf(sx.y);
            h.z = tanhf(sx.z); h.w = tanhf(sx.w);
            size_t dst = (size_t)brow * Hc + bcol;
            *(float4*)&g_hall[(size_t)t * (Bc * Hc) + dst] = h;
            // split + pack for next step's bf16x3 phase A (ring slot t&1)
            uint32_t hi01, lo01, hi23, lo23;
            split_bf16x2(h.x, h.y, hi01, lo01);
            split_bf16x2(h.z, h.w, hi23, lo23);
            size_t rb = (size_t)(t & 1) * (Bc * H2)
                      + (size_t)brow * H2 + (bcol >> 1);
            *(uint2*)&g_hpk_hi[rb] = make_uint2(hi01, hi23);
            *(uint2*)&g_hpk_lo[rb] = make_uint2(lo01, lo23);
        }

        // ---- grid barrier 2 ----
        target += NCTA;
        __syncthreads();
        if (tid == 0) {
            __threadfence();
            atomicAdd(&g_bar, 1u);
            while (*((volatile unsigned*)&g_bar) < target) { }
            __threadfence();
        }
        __syncthreads();
    }
}

// ---------------------------------------------------------------------------
extern "C" void kernel_launch(void* const* d_in, const int* in_sizes, int n_in,
                              void* d_out, int out_size) {
    const float* x    = (const float*)d_in[0];  // [64,512,512]
    const float* W_xh = (const float*)d_in[1];  // [512,1024]
    const float* W_hh = (const float*)d_in[2];  // [1024,1024]
    const float* b_h  = (const float*)d_in[3];  // [1024]
    const float* W_hy = (const float*)d_in[4];  // [1024,512]
    const float* b_y  = (const float*)d_in[5];  // [512]
    float* out = (float*)d_out;                 // [64,512,512]

    // smem: W hi/lo [128][36] + h hi/lo [64][36]  (uint32)
    const int rnn_smem = (2 * 128 * 36 + 2 * 64 * 36) * (int)sizeof(uint32_t);

    static bool attr_set = false;
    if (!attr_set) {
        cudaFuncSetAttribute(k_rnn, cudaFuncAttributeMaxDynamicSharedMemorySize,
                             rnn_smem);
        attr_set = true;
    }

    k_init<<<1, 32>>>();

    // xW projection: M=32768, N=1024 (tf32 MMA)
    dim3 gx(Hc / 128, (Bc * Tc) / 128);
    k_gemm_xw<<<gx, 256>>>(x, W_xh, b_h);

    // recurrence: persistent, 128 CTAs, two-phase K-split (bf16x3 MMA)
    k_rnn<<<NCTA, 256, rnn_smem>>>(W_hh);

    // output projection: M=32768, N=512 (tf32 MMA)
    dim3 gy(Oc / 128, (Bc * Tc) / 128);
    k_gemm_y<<<gy, 256>>>(W_hy, b_y, out);
}

// round 14
// speedup vs baseline: 3.1314x; 1.0446x over previous
#include <cuda_runtime.h>
#include <math.h>
#include <stdint.h>

// Problem dims
#define Bc 64
#define Tc 512
#define Ic 512
#define Hc 1024
#define Oc 512
#define NCTA 128   // persistent grid (<=148 SMs -> all co-resident)

// Recurrence decomposition
#define NT 8       // column tiles of 128
#define KC 16      // K chunks of 64
#define KCH 64     // k per chunk
#define CT 128     // cols per tile
#define H2 (Hc/2)  // packed bf16x2 pairs per row

// ---- tf32 helpers (big GEMMs) ----
__device__ __forceinline__ uint32_t f2tf32(float x) {
    uint32_t r; asm("cvt.rna.tf32.f32 %0, %1;" : "=r"(r) : "f"(x)); return r;
}
__device__ __forceinline__ void mma_tf32(float* c,
                                         const uint32_t* a, const uint32_t* b) {
    asm("mma.sync.aligned.m16n8k8.row.col.f32.tf32.tf32.f32 "
        "{%0,%1,%2,%3}, {%4,%5,%6,%7}, {%8,%9}, {%0,%1,%2,%3};"
        : "+f"(c[0]), "+f"(c[1]), "+f"(c[2]), "+f"(c[3])
        : "r"(a[0]), "r"(a[1]), "r"(a[2]), "r"(a[3]), "r"(b[0]), "r"(b[1]));
}

// ---- bf16 helpers (recurrence) ----
__device__ __forceinline__ void split_bf16x2(float x, float y,
                                             uint32_t& hi, uint32_t& lo) {
    uint32_t h;
    asm("cvt.rn.bf16x2.f32 %0, %1, %2;" : "=r"(h) : "f"(y), "f"(x));
    float xh = __uint_as_float(h << 16);
    float yh = __uint_as_float(h & 0xFFFF0000u);
    asm("cvt.rn.bf16x2.f32 %0, %1, %2;" : "=r"(lo) : "f"(y - yh), "f"(x - xh));
    hi = h;
}
__device__ __forceinline__ void mma_bf16(float* c,
                                         const uint32_t* a, const uint32_t* b) {
    asm("mma.sync.aligned.m16n8k16.row.col.f32.bf16.bf16.f32 "
        "{%0,%1,%2,%3}, {%4,%5,%6,%7}, {%8,%9}, {%0,%1,%2,%3};"
        : "+f"(c[0]), "+f"(c[1]), "+f"(c[2]), "+f"(c[3])
        : "r"(a[0]), "r"(a[1]), "r"(a[2]), "r"(a[3]), "r"(b[0]), "r"(b[1]));
}
__device__ __forceinline__ void ldsm_x4(uint32_t* r, uint32_t addr) {
    asm volatile("ldmatrix.sync.aligned.m8n8.x4.shared.b16 {%0,%1,%2,%3}, [%4];"
        : "=r"(r[0]), "=r"(r[1]), "=r"(r[2]), "=r"(r[3]) : "r"(addr));
}
__device__ __forceinline__ uint32_t smem_u32(const void* p) {
    uint32_t a;
    asm("{ .reg .u64 t; cvta.to.shared.u64 t, %1; cvt.u32.u64 %0, t; }"
        : "=r"(a) : "l"(p));
    return a;
}

// Scratch (static __device__ allowed; cudaMalloc is not)
__device__ float g_xw[Tc * Bc * Hc];        // [t][b][h]  x@W_xh + b_h
__device__ float g_hall[Tc * Bc * Hc];      // [t][b][h]  hidden states (fp32)
__device__ float g_part[KC * Bc * Hc];      // [kc][b][h] per-K-chunk partials
__device__ uint32_t g_hpk_hi[2 * Bc * H2];  // ring: packed bf16x2 hi of h
__device__ uint32_t g_hpk_lo[2 * Bc * H2];  // ring: packed bf16x2 lo of h
__device__ unsigned g_bar;

// ---------------------------------------------------------------------------
__global__ void k_init() {
    if (threadIdx.x == 0) g_bar = 0u;
}

// ---------------------------------------------------------------------------
// Shared tf32 GEMM body (unchanged, known-good 278us)
// ---------------------------------------------------------------------------
#define GEMM_TF32_BODY(Aptr, Bptr, Kdim, Ndim)                                  \
    __shared__ uint32_t As[128][20];                                            \
    __shared__ uint32_t Bs[16][136];                                            \
    const int tid  = threadIdx.x;                                               \
    const int lane = tid & 31;                                                  \
    const int warp = tid >> 5;                                                  \
    const int wm = warp & 1, wn = warp >> 1;                                    \
    const int m0 = blockIdx.y * 128;                                            \
    const int n0 = blockIdx.x * 128;                                            \
    float acc[4][4][4];                                                         \
    _Pragma("unroll") for (int mi = 0; mi < 4; ++mi)                            \
    _Pragma("unroll") for (int ni = 0; ni < 4; ++ni)                            \
    _Pragma("unroll") for (int q = 0; q < 4; ++q) acc[mi][ni][q] = 0.f;         \
    for (int k0 = 0; k0 < (Kdim); k0 += 16) {                                   \
        float4 av[2], bv[2];                                                    \
        int arow[2], akq[2], brow[2], bnq[2];                                   \
        _Pragma("unroll") for (int i = 0; i < 2; ++i) {                         \
            int g = tid + i * 256;                                              \
            arow[i] = g >> 2; akq[i] = (g & 3) * 4;                             \
            av[i] = *(const float4*)&(Aptr)[(size_t)(m0 + arow[i]) * (Kdim)     \
                                            + k0 + akq[i]];                     \
            brow[i] = g >> 5; bnq[i] = (g & 31) * 4;                            \
            bv[i] = *(const float4*)&(Bptr)[(size_t)(k0 + brow[i]) * (Ndim)     \
                                            + n0 + bnq[i]];                     \
        }                                                                       \
        __syncthreads();                                                        \
        _Pragma("unroll") for (int i = 0; i < 2; ++i) {                         \
            uint4 ua = make_uint4(f2tf32(av[i].x), f2tf32(av[i].y),             \
                                  f2tf32(av[i].z), f2tf32(av[i].w));            \
            *(uint4*)&As[arow[i]][akq[i]] = ua;                                 \
            uint4 ub = make_uint4(f2tf32(bv[i].x), f2tf32(bv[i].y),             \
                                  f2tf32(bv[i].z), f2tf32(bv[i].w));            \
            *(uint4*)&Bs[brow[i]][bnq[i]] = ub;                                 \
        }                                                                       \
        __syncthreads();                                                        \
        _Pragma("unroll") for (int kb = 0; kb < 16; kb += 8) {                  \
            uint32_t afr[4][4];                                                 \
            _Pragma("unroll") for (int mi = 0; mi < 4; ++mi) {                  \
                int r = (lane >> 2) + mi * 16 + wm * 64;                        \
                int kk = kb + (lane & 3);                                       \
                afr[mi][0] = As[r][kk];                                         \
                afr[mi][1] = As[r + 8][kk];                                     \
                afr[mi][2] = As[r][kk + 4];                                     \
                afr[mi][3] = As[r + 8][kk + 4];                                 \
            }                                                                   \
            uint32_t bfr[4][2];                                                 \
            _Pragma("unroll") for (int ni = 0; ni < 4; ++ni) {                  \
                int c = (lane >> 2) + ni * 8 + wn * 32;                         \
                bfr[ni][0] = Bs[kb + (lane & 3)][c];                            \
                bfr[ni][1] = Bs[kb + (lane & 3) + 4][c];                        \
            }                                                                   \
            _Pragma("unroll") for (int mi = 0; mi < 4; ++mi)                    \
            _Pragma("unroll") for (int ni = 0; ni < 4; ++ni)                    \
                mma_tf32(acc[mi][ni], afr[mi], bfr[ni]);                        \
        }                                                                       \
    }

// GEMM 1: g_xw[t*B+b][h] = x[b*T+t][:] @ W_xh + b_h.  M=32768,N=1024,K=512
__global__ void __launch_bounds__(256) k_gemm_xw(const float* __restrict__ A,
                                                 const float* __restrict__ Bm,
                                                 const float* __restrict__ bias) {
    GEMM_TF32_BODY(A, Bm, Ic, Hc)
#pragma unroll
    for (int mi = 0; mi < 4; ++mi)
#pragma unroll
        for (int ni = 0; ni < 4; ++ni) {
            int r = m0 + wm * 64 + mi * 16 + (lane >> 2);
            int c = n0 + wn * 32 + ni * 8 + 2 * (lane & 3);
            float bx = bias[c], by = bias[c + 1];
            int b1i = r >> 9, t1i = r & 511;
            float* d0 = g_xw + (size_t)(t1i * Bc + b1i) * Hc + c;
            d0[0] = acc[mi][ni][0] + bx; d0[1] = acc[mi][ni][1] + by;
            int r2 = r + 8;
            int b2i = r2 >> 9, t2i = r2 & 511;
            float* d1 = g_xw + (size_t)(t2i * Bc + b2i) * Hc + c;
            d1[0] = acc[mi][ni][2] + bx; d1[1] = acc[mi][ni][3] + by;
        }
}

// GEMM 2: out[b][t][o] = g_hall[t*B+b][:] @ W_hy + b_y.  M=32768,N=512,K=1024
__global__ void __launch_bounds__(256) k_gemm_y(const float* __restrict__ Bm,
                                                const float* __restrict__ bias,
                                                float* __restrict__ out) {
    const float* A = g_hall;
    GEMM_TF32_BODY(A, Bm, Hc, Oc)
#pragma unroll
    for (int mi = 0; mi < 4; ++mi)
#pragma unroll
        for (int ni = 0; ni < 4; ++ni) {
            int r = m0 + wm * 64 + mi * 16 + (lane >> 2);
            int c = n0 + wn * 32 + ni * 8 + 2 * (lane & 3);
            float bx = bias[c], by = bias[c + 1];
            int t1i = r >> 6, b1i = r & 63;
            float* d0 = out + ((size_t)b1i * Tc + t1i) * Oc + c;
            d0[0] = acc[mi][ni][0] + bx; d0[1] = acc[mi][ni][1] + by;
            int r2 = r + 8;
            int t2i = r2 >> 6, b2i = r2 & 63;
            float* d1 = out + ((size_t)b2i * Tc + t2i) * Oc + c;
            d1[0] = acc[mi][ni][2] + bx; d1[1] = acc[mi][ni][3] + by;
        }
}

// ---------------------------------------------------------------------------
// Persistent recurrence, K-split two-phase, bf16x3 m16n8k16, ldmatrix frags.
// CTA (jt, kc): partial[64][128] = h_prev[:, kc*64:+64] @ Whh[kc*64:+64, jt*128:+128]
// h@W ~= hi@Wh + hi@Wl + lo@Wh (exact splits; missing lo@Wl ~ 2^-18 rel).
// Layouts: W hi/lo [128 n][36 k2] words; h hi/lo [64 r][36 k2] words.
// Row stride 36 words -> each ldmatrix 8-row phase hits banks 0,4,..28: clean.
// ---------------------------------------------------------------------------
__global__ void __launch_bounds__(256, 1) k_rnn(const float* __restrict__ Whh) {
    extern __shared__ uint32_t smu[];
    uint32_t* w_hi = smu;                       // [128][36]
    uint32_t* w_lo = smu + 128 * 36;            // [128][36]
    uint32_t* h_hi = smu + 2 * 128 * 36;        // [64][36]
    uint32_t* h_lo = smu + 2 * 128 * 36 + 64 * 36;

    const int tid  = threadIdx.x;
    const int lane = tid & 31;
    const int warp = tid >> 5;                  // 0..7 -> 16 cols each
    const int cta = blockIdx.x;
    const int jt = cta & (NT - 1);              // 0..7
    const int kc = cta >> 3;                    // 0..15

    // Preload W_hh slice, split + pack (k even -> lower, k+1 -> upper)
    for (int e = tid; e < CT * (KCH / 2); e += 256) {
        int n = e & 127, k2 = e >> 7;           // k2 0..31
        const float* wp = Whh + (size_t)(kc * KCH + 2 * k2) * Hc + jt * CT + n;
        uint32_t hi, lo;
        split_bf16x2(wp[0], wp[Hc], hi, lo);
        w_hi[n * 36 + k2] = hi;
        w_lo[n * 36 + k2] = lo;
    }

    // smem u32 bases for ldmatrix
    const uint32_t sb     = smem_u32(smu);
    const uint32_t sb_whi = sb;
    const uint32_t sb_wlo = sb + 128 * 36 * 4;
    const uint32_t sb_hhi = sb + 2 * 128 * 36 * 4;
    const uint32_t sb_hlo = sb_hhi + 64 * 36 * 4;

    // per-lane ldmatrix byte offsets (constant across slabs)
    // A (m16k16 x4): lanes 0-7 rows 0-7 kh0 | 8-15 rows 8-15 kh0
    //                | 16-23 rows 0-7 kh1 | 24-31 rows 8-15 kh1
    const uint32_t a_loff = (uint32_t)(((lane & 15) * 36 + (lane >> 4) * 4) * 4);
    // B (n16k16 x4): lanes 0-7 n0-7 kh0 | 8-15 n0-7 kh1
    //                | 16-23 n8-15 kh0 | 24-31 n8-15 kh1
    const uint32_t b_loff = (uint32_t)(
        ((((lane & 7) + ((lane >> 4) & 1) * 8) * 36) + ((lane >> 3) & 1) * 4) * 4);
    const uint32_t b_warp = (uint32_t)(warp * 16 * 36 * 4);

    // Phase B mapping: all 32768 threads, each 1 row x 2 cols of h
    const int gid = cta * 256 + tid;
    const int brow = gid >> 9;                  // 0..63
    const int bcol = (gid & 511) * 2;           // 0..1022

    unsigned target = 0;

    for (int t = 0; t < Tc; ++t) {
        // ================= Phase A =================
        if (t > 0) {
            const int ring = (t - 1) & 1;
            const uint32_t* phi = g_hpk_hi + (size_t)ring * (Bc * H2);
            const uint32_t* plo = g_hpk_lo + (size_t)ring * (Bc * H2);
#pragma unroll
            for (int i = 0; i < 2; ++i) {
                int g = tid + i * 256;          // 512 uint4 groups
                int r = g >> 3, kq = (g & 7) * 4;
                size_t src = (size_t)r * H2 + kc * (KCH / 2) + kq;
                // __ldcg: ring addresses repeat every 2 steps; bypass L1
                uint4 vh = __ldcg((const uint4*)(phi + src));
                uint4 vl = __ldcg((const uint4*)(plo + src));
                *(uint4*)&h_hi[r * 36 + kq] = vh;
                *(uint4*)&h_lo[r * 36 + kq] = vl;
            }
            __syncthreads();

            float acc[4][2][4];
#pragma unroll
            for (int mi = 0; mi < 4; ++mi)
#pragma unroll
                for (int ni = 0; ni < 2; ++ni)
#pragma unroll
                    for (int q = 0; q < 4; ++q) acc[mi][ni][q] = 0.f;

#pragma unroll
            for (int s = 0; s < 4; ++s) {       // four k16 slabs
                const uint32_t soff = (uint32_t)(8 * s * 4);
                uint32_t ahi[4][4], alo[4][4];
#pragma unroll
                for (int mi = 0; mi < 4; ++mi) {
                    const uint32_t moff = (uint32_t)(mi * 16 * 36 * 4);
                    ldsm_x4(ahi[mi], sb_hhi + moff + soff + a_loff);
                    ldsm_x4(alo[mi], sb_hlo + moff + soff + a_loff);
                }
                uint32_t bhi[4], blo[4];
                ldsm_x4(bhi, sb_whi + b_warp + soff + b_loff);
                ldsm_x4(blo, sb_wlo + b_warp + soff + b_loff);
#pragma unroll
                for (int mi = 0; mi < 4; ++mi)
#pragma unroll
                    for (int ni = 0; ni < 2; ++ni) {
                        mma_bf16(acc[mi][ni], ahi[mi], &bhi[2 * ni]); // hi*Whi
                        mma_bf16(acc[mi][ni], ahi[mi], &blo[2 * ni]); // hi*Wlo
                        mma_bf16(acc[mi][ni], alo[mi], &bhi[2 * ni]); // lo*Whi
                    }
            }
            // write partials: g_part[kc][row][jt*128 + col]
#pragma unroll
            for (int mi = 0; mi < 4; ++mi)
#pragma unroll
                for (int ni = 0; ni < 2; ++ni) {
                    int row = (lane >> 2) + mi * 16;
                    int col = warp * 16 + ni * 8 + 2 * (lane & 3);
                    float* p = g_part + (size_t)kc * (Bc * Hc)
                             + (size_t)row * Hc + jt * CT + col;
                    *(float2*)p = make_float2(acc[mi][ni][0], acc[mi][ni][1]);
                    *(float2*)(p + 8 * Hc) =
                        make_float2(acc[mi][ni][2], acc[mi][ni][3]);
                }
        }

        // prefetch xw for phase B (independent; hides under barrier)
        float2 sx = *(const float2*)(g_xw + (size_t)t * (Bc * Hc) +
                                     (size_t)brow * Hc + bcol);

        // ---- grid barrier 1 ----
        target += NCTA;
        __syncthreads();
        if (tid == 0) {
            __threadfence();
            atomicAdd(&g_bar, 1u);
            while (*((volatile unsigned*)&g_bar) < target) { }
            __threadfence();
        }
        __syncthreads();

        // ================= Phase B =================
        {
            if (t > 0) {
                const float* pb = g_part + (size_t)brow * Hc + bcol;
#pragma unroll
                for (int k2 = 0; k2 < KC; ++k2) {
                    float2 p = __ldcg((const float2*)(pb + (size_t)k2 * (Bc * Hc)));
                    sx.x += p.x; sx.y += p.y;
                }
            }
            float hx = tanhf(sx.x), hy = tanhf(sx.y);
            size_t dst = (size_t)brow * Hc + bcol;
            *(float2*)&g_hall[(size_t)t * (Bc * Hc) + dst] = make_float2(hx, hy);
            // split + pack for next step's bf16x3 phase A (ring slot t&1)
            uint32_t hi01, lo01;
            split_bf16x2(hx, hy, hi01, lo01);
            size_t rb = (size_t)(t & 1) * (Bc * H2)
                      + (size_t)brow * H2 + (bcol >> 1);
            g_hpk_hi[rb] = hi01;
            g_hpk_lo[rb] = lo01;
        }

        // ---- grid barrier 2 ----
        target += NCTA;
        __syncthreads();
        if (tid == 0) {
            __threadfence();
            atomicAdd(&g_bar, 1u);
            while (*((volatile unsigned*)&g_bar) < target) { }
            __threadfence();
        }
        __syncthreads();
    }
}

// ---------------------------------------------------------------------------
extern "C" void kernel_launch(void* const* d_in, const int* in_sizes, int n_in,
                              void* d_out, int out_size) {
    const float* x    = (const float*)d_in[0];  // [64,512,512]
    const float* W_xh = (const float*)d_in[1];  // [512,1024]
    const float* W_hh = (const float*)d_in[2];  // [1024,1024]
    const float* b_h  = (const float*)d_in[3];  // [1024]
    const float* W_hy = (const float*)d_in[4];  // [1024,512]
    const float* b_y  = (const float*)d_in[5];  // [512]
    float* out = (float*)d_out;                 // [64,512,512]

    // smem: W hi/lo [128][36] + h hi/lo [64][36]  (uint32)
    const int rnn_smem = (2 * 128 * 36 + 2 * 64 * 36) * (int)sizeof(uint32_t);

    static bool attr_set = false;
    if (!attr_set) {
        cudaFuncSetAttribute(k_rnn, cudaFuncAttributeMaxDynamicSharedMemorySize,
                             rnn_smem);
        attr_set = true;
    }

    k_init<<<1, 32>>>();

    // xW projection: M=32768, N=1024 (tf32 MMA)
    dim3 gx(Hc / 128, (Bc * Tc) / 128);
    k_gemm_xw<<<gx, 256>>>(x, W_xh, b_h);

    // recurrence: persistent, 128 CTAs, two-phase K-split (bf16x3 + ldmatrix)
    k_rnn<<<NCTA, 256, rnn_smem>>>(W_hh);

    // output projection: M=32768, N=512 (tf32 MMA)
    dim3 gy(Oc / 128, (Bc * Tc) / 128);
    k_gemm_y<<<gy, 256>>>(W_hy, b_y, out);
}